// round 2
// baseline (speedup 1.0000x reference)
#include <cuda_runtime.h>

#define NODES 336
#define NPC   8192
#define NUMCASE 2048
#define MIU_F 1.9e-05f
#define ALPHA_F 0.10471975511965977f   // 6*pi/180

// 0.5 * 1.225 * ACOUSTIC^2, ACOUSTIC = sqrt(1.4*287*300) -> 0.6125 * 120540
#define QCOEF_F 73830.75f

// design slab per case: NODES*5 floats = 1680 floats = 420 float4
#define DSG_F4 420

__global__ __launch_bounds__(352) void dyn_kernel(
    const float* __restrict__ coords,
    const float* __restrict__ fields,
    const float* __restrict__ design,
    float2* __restrict__ out)
{
    const int c = blockIdx.x;
    const int base = c * NPC;
    const int i = threadIdx.x;

    __shared__ float2 s_n0[NODES];
    __shared__ float  s_tau[NODES];
    __shared__ float  s_red[11][4];

    float2 n0 = make_float2(0.f, 0.f);
    float2 n1 = make_float2(0.f, 0.f);
    float f1u = 0.f, f1v = 0.f;
    float ptv = 0.f;
    float d3 = 0.f, d4 = 0.f;

    // ---- dense design slab: 420 float4, all components, mod-5 select ----
    {
        const float4* dsg4 = (const float4*)design + (size_t)c * (NPC * 5 / 4);
        #pragma unroll
        for (int k = 0; k < 2; k++) {
            int t = i + k * 352;
            if (t < DSG_F4) {
                float4 v = __ldg(&dsg4[t]);
                int g0 = 4 * t;
                int r = g0 % 5;                   // component index of v.x
                float vv[4] = {v.x, v.y, v.z, v.w};
                #pragma unroll
                for (int j = 0; j < 4; j++) {
                    int comp = r + j; if (comp >= 5) comp -= 5;
                    if (comp == 3) d3 += vv[j];
                    else if (comp == 4) d4 += vv[j];
                }
            }
        }
    }

    if (i < NODES) {
        const float2* cf2 = (const float2*)coords;
        n0 = cf2[base + i];
        n1 = cf2[base + NODES + i];
        s_n0[i] = n0;
        float4 f1 = ((const float4*)fields)[base + NODES + i];
        f1u = f1.z;
        f1v = f1.w;
        float4 f0 = ((const float4*)fields)[base + i];
        ptv = f0.x;                               // f0[:, :, 0]
    }
    __syncthreads();

    float Tx = 0.f, Ty = 0.f;
    if (i < NODES) {
        int ip = (i + 1 == NODES) ? 0 : i + 1;
        float2 n0p = s_n0[ip];
        Tx = n0p.x - n0.x;
        Ty = n0p.y - n0.y;
        float Tn = sqrtf(Tx * Tx + Ty * Ty);
        float du = (f1u * Tx + f1v * Ty) / Tn;
        float dx = n1.x - n0.x, dy = n1.y - n0.y;
        float delta = sqrtf(dx * dx + dy * dy);
        s_tau[i] = MIU_F * du / delta;
    }
    __syncthreads();

    float Fx = 0.f, Fy = 0.f;
    if (i < NODES) {
        int ip = (i + 1 == NODES) ? 0 : i + 1;
        float tau_ave = 0.5f * (s_tau[i] + s_tau[ip]);
        // -Px = -pt*T.y ; -Py = +pt*T.x ; Tx_f = 50*tau_ave*T.x ; Ty_f = 50*tau_ave*T.y
        Fx = -ptv * Ty + 50.f * tau_ave * Tx;
        Fy =  ptv * Tx + 50.f * tau_ave * Ty;
    }

    // Block reduction of (Fx, Fy, d3, d4)
    #pragma unroll
    for (int off = 16; off; off >>= 1) {
        Fx += __shfl_down_sync(0xffffffffu, Fx, off);
        Fy += __shfl_down_sync(0xffffffffu, Fy, off);
        d3 += __shfl_down_sync(0xffffffffu, d3, off);
        d4 += __shfl_down_sync(0xffffffffu, d4, off);
    }
    int warp = i >> 5, lane = i & 31;
    if (lane == 0) {
        s_red[warp][0] = Fx;
        s_red[warp][1] = Fy;
        s_red[warp][2] = d3;
        s_red[warp][3] = d4;
    }
    __syncthreads();

    if (i == 0) {
        float fx = 0.f, fy = 0.f, s3 = 0.f, s4 = 0.f;
        #pragma unroll
        for (int w = 0; w < 11; w++) {
            fx += s_red[w][0];
            fy += s_red[w][1];
            s3 += s_red[w][2];
            s4 += s_red[w][3];
        }
        float Ma = s3 * (0.3f / (float)NODES) + 0.3f;
        float af = s4 * (ALPHA_F / (float)NODES);
        float ca = cosf(af), sa = sinf(af);
        float Fxn = fx * ca + fy * sa;
        float Fyn = fy * ca - Fxn * sa;   // reference uses Fx_new here (literal)
        float q = QCOEF_F * Ma * Ma;
        out[c] = make_float2(Fxn / q, Fyn / q);
    }
}

extern "C" void kernel_launch(void* const* d_in, const int* in_sizes, int n_in,
                              void* d_out, int out_size) {
    // metadata order: batch(int32), coords(f32), fields(f32), design(f32), num_case, nodes_num
    const float* coords = (const float*)d_in[1];
    const float* fields = (const float*)d_in[2];
    const float* design = (const float*)d_in[3];
    float2* out = (float2*)d_out;
    dyn_kernel<<<NUMCASE, 352>>>(coords, fields, design, out);
}

// round 3
// speedup vs baseline: 1.3488x; 1.3488x over previous
#include <cuda_runtime.h>

#define NODES 336
#define NPC   8192
#define NUMCASE 2048
#define MIU_F 1.9e-05f
#define ALPHA_F 0.10471975511965977f   // 6*pi/180
#define QCOEF_F 73830.75f              // 0.5*1.225*ACOUSTIC^2

__global__ __launch_bounds__(128) void dyn_kernel(
    const float* __restrict__ coords,
    const float* __restrict__ fields,
    const float* __restrict__ design,
    float2* __restrict__ out)
{
    const int c = blockIdx.x;
    const int base = c * NPC;
    const int t = threadIdx.x;

    __shared__ float2 s_n0[NODES];
    __shared__ float  s_tau[NODES];
    __shared__ float  s_red[4][4];

    // thread t handles nodes t, t+128, t+256(if <336)
    float2 n0[3], n1[3];
    float f1u[3], f1v[3], pt[3];
    float d3 = 0.f, d4 = 0.f;

    const float2* cf2 = (const float2*)coords;
    const float4* ff4 = (const float4*)fields;

    // ---- Phase 0: front-batched independent loads (max MLP) ----
    #pragma unroll
    for (int k = 0; k < 3; k++) {
        int j = t + k * 128;
        bool valid = (k < 2) || (t < NODES - 256);
        if (valid) {
            n0[k] = cf2[base + j];
            n1[k] = cf2[base + NODES + j];
            float4 f1 = ff4[base + NODES + j];
            f1u[k] = f1.z;
            f1v[k] = f1.w;
            pt[k]  = fields[4 * (base + j)];          // f0[:, :, 0]
            d3 += design[5 * (base + j) + 3];
            d4 += design[5 * (base + j) + 4];
            s_n0[j] = n0[k];
        }
    }
    __syncthreads();

    // ---- Phase 1: T and tau ----
    float Tx[3], Ty[3];
    #pragma unroll
    for (int k = 0; k < 3; k++) {
        int j = t + k * 128;
        bool valid = (k < 2) || (t < NODES - 256);
        if (valid) {
            int jp = (j + 1 == NODES) ? 0 : j + 1;
            float2 np = s_n0[jp];
            Tx[k] = np.x - n0[k].x;
            Ty[k] = np.y - n0[k].y;
            float Tn = sqrtf(Tx[k] * Tx[k] + Ty[k] * Ty[k]);
            float du = (f1u[k] * Tx[k] + f1v[k] * Ty[k]) / Tn;
            float dx = n1[k].x - n0[k].x, dy = n1[k].y - n0[k].y;
            float delta = sqrtf(dx * dx + dy * dy);
            s_tau[j] = MIU_F * du / delta;
        }
    }
    __syncthreads();

    // ---- Phase 2: forces ----
    float Fx = 0.f, Fy = 0.f;
    #pragma unroll
    for (int k = 0; k < 3; k++) {
        int j = t + k * 128;
        bool valid = (k < 2) || (t < NODES - 256);
        if (valid) {
            int jp = (j + 1 == NODES) ? 0 : j + 1;
            float tau_ave = 0.5f * (s_tau[j] + s_tau[jp]);
            // -Px = -pt*T.y ; -Py = +pt*T.x ; +50*tau_ave*T
            Fx += -pt[k] * Ty[k] + 50.f * tau_ave * Tx[k];
            Fy +=  pt[k] * Tx[k] + 50.f * tau_ave * Ty[k];
        }
    }

    // ---- Block reduction over 4 warps ----
    #pragma unroll
    for (int off = 16; off; off >>= 1) {
        Fx += __shfl_down_sync(0xffffffffu, Fx, off);
        Fy += __shfl_down_sync(0xffffffffu, Fy, off);
        d3 += __shfl_down_sync(0xffffffffu, d3, off);
        d4 += __shfl_down_sync(0xffffffffu, d4, off);
    }
    int warp = t >> 5, lane = t & 31;
    if (lane == 0) {
        s_red[warp][0] = Fx;
        s_red[warp][1] = Fy;
        s_red[warp][2] = d3;
        s_red[warp][3] = d4;
    }
    __syncthreads();

    if (t == 0) {
        float fx = 0.f, fy = 0.f, s3 = 0.f, s4 = 0.f;
        #pragma unroll
        for (int w = 0; w < 4; w++) {
            fx += s_red[w][0];
            fy += s_red[w][1];
            s3 += s_red[w][2];
            s4 += s_red[w][3];
        }
        float Ma = s3 * (0.3f / (float)NODES) + 0.3f;
        float af = s4 * (ALPHA_F / (float)NODES);
        float ca = cosf(af), sa = sinf(af);
        float Fxn = fx * ca + fy * sa;
        float Fyn = fy * ca - Fxn * sa;   // reference uses Fx_new here (literal)
        float q = QCOEF_F * Ma * Ma;
        out[c] = make_float2(Fxn / q, Fyn / q);
    }
}

extern "C" void kernel_launch(void* const* d_in, const int* in_sizes, int n_in,
                              void* d_out, int out_size) {
    // metadata order: batch(int32), coords(f32), fields(f32), design(f32), num_case, nodes_num
    const float* coords = (const float*)d_in[1];
    const float* fields = (const float*)d_in[2];
    const float* design = (const float*)d_in[3];
    float2* out = (float2*)d_out;
    dyn_kernel<<<NUMCASE, 128>>>(coords, fields, design, out);
}